// round 2
// baseline (speedup 1.0000x reference)
#include <cuda_runtime.h>
#include <math.h>

#define NN 100000
#define NE 1600000
#define DIM 64

typedef unsigned long long u64t;

// -------- scratch (static device globals; no runtime allocation) --------
__device__ float d_Q[(size_t)NN * DIM];   // 25.6 MB
__device__ float d_K[(size_t)NN * DIM];   // 25.6 MB
__device__ float d_g[NN];                 // per-node gate scalar
__device__ float d_denom[NN];             // softmax denominators
__device__ float d_wvf[DIM];              // Wv @ wF
__device__ float d_c2;                    // bv·wF + bF

// -------- packed f32x2 helpers --------
__device__ __forceinline__ void ffma2(u64t& d, u64t a, u64t b) {
    asm("fma.rn.f32x2 %0, %1, %2, %0;" : "+l"(d) : "l"(a), "l"(b));
}
__device__ __forceinline__ u64t mul2(u64t a, u64t b) {
    u64t d; asm("mul.rn.f32x2 %0, %1, %2;" : "=l"(d) : "l"(a), "l"(b)); return d;
}
__device__ __forceinline__ u64t add2(u64t a, u64t b) {
    u64t d; asm("add.rn.f32x2 %0, %1, %2;" : "=l"(d) : "l"(a), "l"(b)); return d;
}
__device__ __forceinline__ u64t pack2f(float x, float y) {
    u64t r;
    asm("mov.b64 %0, {%1, %2};" : "=l"(r)
        : "r"(__float_as_uint(x)), "r"(__float_as_uint(y)));
    return r;
}
__device__ __forceinline__ u64t pack2(float v) { return pack2f(v, v); }
__device__ __forceinline__ float2 unpack2(u64t v) {
    unsigned lo, hi;
    asm("mov.b64 {%0, %1}, %2;" : "=r"(lo), "=r"(hi) : "l"(v));
    return make_float2(__uint_as_float(lo), __uint_as_float(hi));
}
__device__ __forceinline__ float ex2f(float x) {
    float y; asm("ex2.approx.f32 %0, %1;" : "=f"(y) : "f"(x)); return y;
}
__device__ __forceinline__ float rcpf(float x) {
    float y; asm("rcp.approx.f32 %0, %1;" : "=f"(y) : "f"(x)); return y;
}

#define NL2E_PAIR 0xBFB8AA3BBFB8AA3BULL  /* (-log2(e), -log2(e)) */
#define ONE_PAIR  0x3F8000003F800000ULL  /* (1.0f, 1.0f) */

// silu on a packed pair: z * rcp(1 + exp(-z)) per component
__device__ __forceinline__ u64t silu2(u64t z) {
    u64t m = mul2(z, (u64t)NL2E_PAIR);
    float2 mf = unpack2(m);
    u64t d = add2(pack2f(ex2f(mf.x), ex2f(mf.y)), (u64t)ONE_PAIR);
    float2 df = unpack2(d);
    u64t r = pack2f(rcpf(df.x), rcpf(df.y));
    return mul2(z, r);
}

__device__ __forceinline__ float silu_f(float z) {
    float e = ex2f(z * -1.4426950408889634f);
    return z * rcpf(1.0f + e);
}

// -------- K0: zero accumulators, fold Wv@wF --------
__global__ void k_init(const float* __restrict__ Wv, const float* __restrict__ bv,
                       const float* __restrict__ wF, const float* __restrict__ bF,
                       float* __restrict__ out) {
    int t = blockIdx.x * blockDim.x + threadIdx.x;
    if (t < NN) d_denom[t] = 0.0f;
    if (t < 3 * NN) out[t] = 0.0f;
    if (blockIdx.x == 0 && threadIdx.x < DIM) {
        int c = threadIdx.x;
        float s = 0.0f;
        for (int d = 0; d < DIM; ++d) s += Wv[c * DIM + d] * wF[d];
        d_wvf[c] = s;
        if (c == 0) {
            float s2 = bF[0];
            for (int d = 0; d < DIM; ++d) s2 += bv[d] * wF[d];
            d_c2 = s2;
        }
    }
}

// -------- K1: per-node Q, K projections + gate scalar (packed f32x2) --------
__global__ void __launch_bounds__(256) k_nodes(
    const float* __restrict__ x,
    const float* __restrict__ Wq, const float* __restrict__ bq,
    const float* __restrict__ Wk, const float* __restrict__ bk) {

    __shared__ __align__(16) float sWq[DIM * DIM];
    __shared__ __align__(16) float sWk[DIM * DIM];
    __shared__ __align__(16) float sbq[DIM];
    __shared__ __align__(16) float sbk[DIM];
    __shared__ __align__(16) float swvf[DIM];

    for (int idx = threadIdx.x; idx < DIM * DIM; idx += blockDim.x) {
        sWq[idx] = Wq[idx];
        sWk[idx] = Wk[idx];
    }
    if (threadIdx.x < DIM) {
        sbq[threadIdx.x]  = bq[threadIdx.x];
        sbk[threadIdx.x]  = bk[threadIdx.x];
        swvf[threadIdx.x] = d_wvf[threadIdx.x];
    }
    __syncthreads();

    int n = blockIdx.x * blockDim.x + threadIdx.x;
    if (n >= NN) return;

    // x row -> registers
    float xv[DIM];
    const float4* xr = (const float4*)(x + (size_t)n * DIM);
#pragma unroll
    for (int c4 = 0; c4 < 16; ++c4) {
        float4 t = xr[c4];
        xv[4 * c4 + 0] = t.x; xv[4 * c4 + 1] = t.y;
        xv[4 * c4 + 2] = t.z; xv[4 * c4 + 3] = t.w;
    }

    // gate scalar
    float g = d_c2;
#pragma unroll
    for (int c = 0; c < DIM; ++c) g = fmaf(xv[c], swvf[c], g);
    d_g[n] = g;

    u64t* qout = (u64t*)(d_Q + (size_t)n * DIM);
    u64t* kout = (u64t*)(d_K + (size_t)n * DIM);

    // 16 output dims (8 packed pairs) per pass
    for (int db = 0; db < 4; ++db) {
        u64t aq[8], ak[8];
        const u64t* bqp = (const u64t*)(sbq + 16 * db);
        const u64t* bkp = (const u64t*)(sbk + 16 * db);
#pragma unroll
        for (int t = 0; t < 8; ++t) { aq[t] = bqp[t]; ak[t] = bkp[t]; }

#pragma unroll 8
        for (int c = 0; c < DIM; ++c) {
            u64t xc2 = pack2(xv[c]);
            const ulonglong2* wq = (const ulonglong2*)(sWq + c * DIM + 16 * db);
            const ulonglong2* wk = (const ulonglong2*)(sWk + c * DIM + 16 * db);
#pragma unroll
            for (int t = 0; t < 4; ++t) {
                ulonglong2 wa = wq[t];
                ffma2(aq[2 * t + 0], xc2, wa.x);
                ffma2(aq[2 * t + 1], xc2, wa.y);
                ulonglong2 wb = wk[t];
                ffma2(ak[2 * t + 0], xc2, wb.x);
                ffma2(ak[2 * t + 1], xc2, wb.y);
            }
        }
#pragma unroll
        for (int t = 0; t < 8; ++t) {
            qout[8 * db + t] = aq[t];
            kout[8 * db + t] = ak[t];
        }
    }
}

// -------- K2: per-edge MLP + q·k + exp + scatter-add --------
__global__ void __launch_bounds__(256) k_edges(
    const float* __restrict__ edge_vec,
    const int*   __restrict__ eidx,
    const float* __restrict__ W1, const float* __restrict__ b1,
    const float* __restrict__ W2, const float* __restrict__ b2,
    const float* __restrict__ W3, const float* __restrict__ b3,
    float* __restrict__ out) {

    __shared__ __align__(16) float sW2[DIM * DIM];  // [k][d], d contiguous
    __shared__ __align__(16) float sW1[4 * DIM];    // [c][k], k contiguous (pairable)
    __shared__ __align__(16) float sb1[DIM];
    __shared__ __align__(16) float sb2[DIM];
    __shared__ __align__(16) float sW3[DIM];

    for (int idx = threadIdx.x; idx < DIM * DIM; idx += blockDim.x) sW2[idx] = W2[idx];
    for (int idx = threadIdx.x; idx < 4 * DIM; idx += blockDim.x) sW1[idx] = W1[idx];
    if (threadIdx.x < DIM) {
        sb1[threadIdx.x] = b1[threadIdx.x];
        sb2[threadIdx.x] = b2[threadIdx.x];
        sW3[threadIdx.x] = W3[threadIdx.x];
    }
    __syncthreads();

    const float b3v = b3[0];
    const int lane = threadIdx.x & 31;
    const int warp_global = (blockIdx.x * blockDim.x + threadIdx.x) >> 5;
    const int nwarps = (gridDim.x * blockDim.x) >> 5;
    const int ntiles = NE / 32;   // NE divisible by 32

    const u64t* b1p = (const u64t*)sb1;
    const u64t* w1p0 = (const u64t*)(sW1 + 0 * DIM);
    const u64t* w1p1 = (const u64t*)(sW1 + 1 * DIM);
    const u64t* w1p2 = (const u64t*)(sW1 + 2 * DIM);
    const u64t* w1p3 = (const u64t*)(sW1 + 3 * DIM);
    const u64t* w3p = (const u64t*)sW3;

    for (int tile = warp_global; tile < ntiles; tile += nwarps) {
        int e  = tile * 32 + lane;      // this lane's edge
        int ii = eidx[e];               // source node i
        int jj = eidx[NE + e];          // target node j
        float g = d_g[ii];

        // ---- per-lane q[j]·k[i] via packed fma over LDG.128 row loads ----
        const ulonglong2* qp = (const ulonglong2*)(d_Q + (size_t)jj * DIM);
        const ulonglong2* kp = (const ulonglong2*)(d_K + (size_t)ii * DIM);
        u64t da0 = 0, da1 = 0, da2 = 0, da3 = 0;
#pragma unroll
        for (int t = 0; t < 16; ++t) {
            ulonglong2 q = qp[t];
            ulonglong2 k = kp[t];
            if (t & 1) { ffma2(da2, q.x, k.x); ffma2(da3, q.y, k.y); }
            else       { ffma2(da0, q.x, k.x); ffma2(da1, q.y, k.y); }
        }
        float2 ds = unpack2(add2(add2(da0, da1), add2(da2, da3)));
        float dotv = ds.x + ds.y;

        // ---- edge attr ----
        float v0 = edge_vec[3 * e + 0];
        float v1 = edge_vec[3 * e + 1];
        float v2 = edge_vec[3 * e + 2];
        float len = sqrtf(fmaf(v0, v0, fmaf(v1, v1, v2 * v2)));
        u64t v0p = pack2(v0), v1p = pack2(v1), v2p = pack2(v2), lnp = pack2(len);

        // ---- fused MLP: layer-1 + silu (packed pairs), layer-2 f32x2 ----
        u64t acc[32];                              // 64 output dims as f32x2 pairs
        const ulonglong2* b2p = (const ulonglong2*)sb2;
#pragma unroll
        for (int t2 = 0; t2 < 16; ++t2) {
            ulonglong2 b = b2p[t2];
            acc[2 * t2 + 0] = b.x;
            acc[2 * t2 + 1] = b.y;
        }
#pragma unroll 4
        for (int kk = 0; kk < 32; ++kk) {
            u64t zp = b1p[kk];
            ffma2(zp, v0p, w1p0[kk]);
            ffma2(zp, v1p, w1p1[kk]);
            ffma2(zp, v2p, w1p2[kk]);
            ffma2(zp, lnp, w1p3[kk]);
            float2 sf = unpack2(silu2(zp));
            u64t ha = pack2(sf.x);
            u64t hb = pack2(sf.y);
            const ulonglong2* wr0 = (const ulonglong2*)(sW2 + (2 * kk + 0) * DIM);
            const ulonglong2* wr1 = (const ulonglong2*)(sW2 + (2 * kk + 1) * DIM);
#pragma unroll
            for (int t2 = 0; t2 < 16; ++t2) {
                ulonglong2 wa = wr0[t2];
                ffma2(acc[2 * t2 + 0], ha, wa.x);
                ffma2(acc[2 * t2 + 1], ha, wa.y);
                ulonglong2 wb = wr1[t2];
                ffma2(acc[2 * t2 + 0], hb, wb.x);
                ffma2(acc[2 * t2 + 1], hb, wb.y);
            }
        }

        // ---- silu + layer-3 reduction (packed) ----
        u64t biasp = pack2f(b3v, 0.0f);
#pragma unroll
        for (int t = 0; t < 32; ++t) {
            ffma2(biasp, silu2(acc[t]), w3p[t]);
        }
        float2 bf = unpack2(biasp);
        float bias = bf.x + bf.y;

        // ---- score, exp (scores bounded -> no max subtraction needed) ----
        float score = fmaf(dotv, 0.125f, bias);   // 1/sqrt(64)
        float ex = __expf(score);
        float w  = ex * g;

        atomicAdd(&d_denom[jj], ex);
        atomicAdd(out + 3 * jj + 0, w * v0);
        atomicAdd(out + 3 * jj + 1, w * v1);
        atomicAdd(out + 3 * jj + 2, w * v2);
    }
}

// -------- K3: normalize --------
__global__ void k_final(float* __restrict__ out) {
    int n = blockIdx.x * blockDim.x + threadIdx.x;
    if (n < NN) {
        float r = rcpf(d_denom[n] + 1e-16f);
        out[3 * n + 0] *= r;
        out[3 * n + 1] *= r;
        out[3 * n + 2] *= r;
    }
}

// -------- launch --------
extern "C" void kernel_launch(void* const* d_in, const int* in_sizes, int n_in,
                              void* d_out, int out_size) {
    const float* x        = (const float*)d_in[0];
    const float* edge_vec = (const float*)d_in[1];
    const float* Wq = (const float*)d_in[2];
    const float* bq = (const float*)d_in[3];
    const float* Wk = (const float*)d_in[4];
    const float* bk = (const float*)d_in[5];
    const float* Wv = (const float*)d_in[6];
    const float* bv = (const float*)d_in[7];
    const float* W1 = (const float*)d_in[8];
    const float* b1 = (const float*)d_in[9];
    const float* W2 = (const float*)d_in[10];
    const float* b2 = (const float*)d_in[11];
    const float* W3 = (const float*)d_in[12];
    const float* b3 = (const float*)d_in[13];
    const float* wF = (const float*)d_in[14];
    const float* bF = (const float*)d_in[15];
    const int*   ei = (const int*)d_in[16];
    float* out = (float*)d_out;

    k_init <<<(3 * NN + 255) / 256, 256>>>(Wv, bv, wF, bF, out);
    k_nodes<<<(NN + 255) / 256, 256>>>(x, Wq, bq, Wk, bk);
    k_edges<<<1184, 256>>>(edge_vec, ei, W1, b1, W2, b2, W3, b3, out);
    k_final<<<(NN + 255) / 256, 256>>>(out);
}